// round 7
// baseline (speedup 1.0000x reference)
#include <cuda_runtime.h>
#include <cstdint>

#define Bb   4
#define NN   2048
#define FIN  256
#define FOUT 128
#define HH   4
#define NEG  0.2f
#define TK   32
#define NT   (NN / TK)   // 64

// ---------------------------------------------------------------------------
// scratch (no cudaMalloc allowed)
// ---------------------------------------------------------------------------
__device__ float    g_Wh[Bb * NN * FOUT];        // [b][n][o]  4 MB
__device__ float2   g_iAC[Bb * HH * NN];         // (e^el, e^.2el) per (b,h,i)
__device__ float2   g_jEFi[Bb * NN * HH];        // (e^er, e^.2er), [(b*NN+n)*4+h]
__device__ float2   g_irow[Bb * HH * NN];        // prescaled (A*0.25/Z, C*0.25/Z)
__device__ uint32_t g_adjbits[NN * 64];          // 512 KB
__device__ uint4    g_Bfrag4[Bb * NT * 1024];    // Wh B-fragments (tf32), paired

// ---------------------------------------------------------------------------
__device__ __forceinline__ uint32_t f2tf32(float f) {
    uint32_t u;
    asm("cvt.rna.tf32.f32 %0, %1;" : "=r"(u) : "f"(f));
    return u;
}
__device__ __forceinline__ void mma_tf32(float& c0, float& c1, float& c2, float& c3,
                                         uint32_t a0, uint32_t a1, uint32_t a2, uint32_t a3,
                                         uint32_t b0, uint32_t b1) {
    asm volatile("mma.sync.aligned.m16n8k8.row.col.f32.tf32.tf32.f32 "
                 "{%0,%1,%2,%3}, {%4,%5,%6,%7}, {%8,%9}, {%0,%1,%2,%3};"
                 : "+f"(c0), "+f"(c1), "+f"(c2), "+f"(c3)
                 : "r"(a0), "r"(a1), "r"(a2), "r"(a3), "r"(b0), "r"(b1));
}
__device__ __forceinline__ void cp_async16(uint32_t dst, const void* src) {
    asm volatile("cp.async.cg.shared.global [%0], [%1], 16;" :: "r"(dst), "l"(src));
}
#define CP_COMMIT() asm volatile("cp.async.commit_group;" ::: "memory")
#define CP_WAIT0()  asm volatile("cp.async.wait_group 0;" ::: "memory")

// ---------------------------------------------------------------------------
// Kernel 0: adj -> bitmask
// ---------------------------------------------------------------------------
__global__ __launch_bounds__(64) void adjbits_kernel(const int* __restrict__ adj)
{
    const int row = blockIdx.x, w = threadIdx.x;
    const int4* p = (const int4*)(adj + (size_t)row * NN + w * 32);
    uint32_t bits = 0;
#pragma unroll
    for (int q = 0; q < 8; q++) {
        int4 v = __ldg(p + q);
        bits |= (v.x ? 1u : 0u) << (q * 4 + 0);
        bits |= (v.y ? 1u : 0u) << (q * 4 + 1);
        bits |= (v.z ? 1u : 0u) << (q * 4 + 2);
        bits |= (v.w ? 1u : 0u) << (q * 4 + 3);
    }
    g_adjbits[row * 64 + w] = bits;
}

// ---------------------------------------------------------------------------
// Kernel 1: Wh = h @ W^T + b  (register-tiled fp32 GEMM)
// ---------------------------------------------------------------------------
__global__ __launch_bounds__(256) void wh2_kernel(const float* __restrict__ h,
                                                  const float* __restrict__ Ww,
                                                  const float* __restrict__ Wb)
{
    __shared__ float As[32][32];
    __shared__ float Bs[32][128];
    const int t     = threadIdx.x;
    const int grow0 = blockIdx.x * 32;
    const int col   = (t & 31) * 4;
    const int row0  = (t >> 5) * 4;

    float acc[4][4];
#pragma unroll
    for (int r = 0; r < 4; r++)
#pragma unroll
        for (int c = 0; c < 4; c++) acc[r][c] = 0.f;

    for (int kb = 0; kb < FIN; kb += 32) {
        {
            int r = t >> 3, k4 = (t & 7) * 4;
            *(float4*)&As[r][k4] =
                *(const float4*)(h + (size_t)(grow0 + r) * FIN + kb + k4);
        }
        {
            int o = t >> 1, kh = (t & 1) * 16;
#pragma unroll
            for (int s2 = 0; s2 < 4; s2++) {
                float4 v = *(const float4*)(Ww + (size_t)o * FIN + kb + kh + s2 * 4);
                Bs[kh + s2 * 4 + 0][o] = v.x;
                Bs[kh + s2 * 4 + 1][o] = v.y;
                Bs[kh + s2 * 4 + 2][o] = v.z;
                Bs[kh + s2 * 4 + 3][o] = v.w;
            }
        }
        __syncthreads();
#pragma unroll
        for (int k = 0; k < 32; k++) {
            float4 bv = *(const float4*)&Bs[k][col];
            float a0 = As[row0 + 0][k], a1 = As[row0 + 1][k];
            float a2 = As[row0 + 2][k], a3 = As[row0 + 3][k];
            acc[0][0] += a0 * bv.x; acc[0][1] += a0 * bv.y; acc[0][2] += a0 * bv.z; acc[0][3] += a0 * bv.w;
            acc[1][0] += a1 * bv.x; acc[1][1] += a1 * bv.y; acc[1][2] += a1 * bv.z; acc[1][3] += a1 * bv.w;
            acc[2][0] += a2 * bv.x; acc[2][1] += a2 * bv.y; acc[2][2] += a2 * bv.z; acc[2][3] += a2 * bv.w;
            acc[3][0] += a3 * bv.x; acc[3][1] += a3 * bv.y; acc[3][2] += a3 * bv.z; acc[3][3] += a3 * bv.w;
        }
        __syncthreads();
    }

    float4 bias = *(const float4*)(Wb + col);
    const float bc[4] = {bias.x, bias.y, bias.z, bias.w};
#pragma unroll
    for (int r = 0; r < 4; r++) {
        float4 o4 = make_float4(acc[r][0] + bc[0], acc[r][1] + bc[1],
                                acc[r][2] + bc[2], acc[r][3] + bc[3]);
        *(float4*)(g_Wh + (size_t)(grow0 + row0 + r) * FOUT + col) = o4;
    }
}

// ---------------------------------------------------------------------------
// Kernel 2: per (b,h,n): el/er dot products + exps (exact fp32)
// ---------------------------------------------------------------------------
__global__ __launch_bounds__(256) void pack_kernel(const float* __restrict__ attn_w)
{
    const int t    = threadIdx.x;
    const int warp = t >> 5;
    const int lane = t & 31;
    const int row  = blockIdx.x * 8 + warp;
    const int b    = row >> 11;
    const int n    = row & (NN - 1);

    float4 wh = *(const float4*)(g_Wh + (size_t)row * FOUT + lane * 4);
#pragma unroll
    for (int hh = 0; hh < HH; hh++) {
        float4 al = *(const float4*)(attn_w + hh * 2 * FOUT + lane * 4);
        float4 ar = *(const float4*)(attn_w + hh * 2 * FOUT + FOUT + lane * 4);
        float sl = wh.x * al.x + wh.y * al.y + wh.z * al.z + wh.w * al.w;
        float sr = wh.x * ar.x + wh.y * ar.y + wh.z * ar.z + wh.w * ar.w;
#pragma unroll
        for (int off = 16; off > 0; off >>= 1) {
            sl += __shfl_xor_sync(0xffffffffu, sl, off);
            sr += __shfl_xor_sync(0xffffffffu, sr, off);
        }
        if (lane == 0) {
            g_iAC[(b * HH + hh) * NN + n]            = make_float2(expf(sl), expf(NEG * sl));
            g_jEFi[((size_t)(b * NN + n)) * HH + hh] = make_float2(expf(sr), expf(NEG * sr));
        }
    }
}

// ---------------------------------------------------------------------------
// Kernel 3: repack Wh into paired B-fragments (tf32).
// ---------------------------------------------------------------------------
__global__ __launch_bounds__(256) void bfrag_kernel()
{
    const int jt = blockIdx.x, b = blockIdx.y, t = threadIdx.x;
    const size_t base = ((size_t)b * NT + jt) * 1024;
#pragma unroll
    for (int q = 0; q < 4; q++) {
        const int s    = q * 256 + t;
        const int lane = s & 31;
        const int ntp  = (s >> 5) & 7;
        const int ks   = s >> 8;
        const int j    = jt * TK + ks * 8 + (lane & 3);
        const int o0   = (ntp * 2) * 8 + (lane >> 2);
        const int o1   = o0 + 8;
        float x = __ldg(&g_Wh[((size_t)(b * NN + j))     * FOUT + o0]);
        float y = __ldg(&g_Wh[((size_t)(b * NN + j + 4)) * FOUT + o0]);
        float z = __ldg(&g_Wh[((size_t)(b * NN + j))     * FOUT + o1]);
        float w = __ldg(&g_Wh[((size_t)(b * NN + j + 4)) * FOUT + o1]);
        g_Bfrag4[base + s] = make_uint4(f2tf32(x), f2tf32(y), f2tf32(z), f2tf32(w));
    }
}

// ---------------------------------------------------------------------------
// Kernel 4: Z pre-pass (max-trick). Writes g_irow = (A*0.25/Z, C*0.25/Z).
// grid (64, 4), 256 thr: 32 rows/CTA, thread = (i = t>>3, jq = t&7).
// ---------------------------------------------------------------------------
__global__ __launch_bounds__(256) void zsum_kernel()
{
    __shared__ float zr[32][4][8];
    const int t  = threadIdx.x;
    const int b  = blockIdx.y;
    const int i0 = blockIdx.x * 32;
    const int i  = t >> 3, jq = t & 7;
    const int gi = i0 + i;

    float2 AC[4];
#pragma unroll
    for (int h = 0; h < HH; h++) AC[h] = __ldg(&g_iAC[(b * HH + h) * NN + gi]);

    float z0 = 0.f, z1 = 0.f, z2 = 0.f, z3 = 0.f;
    const float4*   src  = (const float4*)(g_jEFi + (size_t)b * NN * HH);
    const uint32_t* mrow = g_adjbits + (size_t)gi * 64;

#pragma unroll 2
    for (int jt = 0; jt < NT; jt++) {
        const uint32_t mw = __ldg(mrow + jt);
#pragma unroll
        for (int e = 0; e < 4; e++) {
            const int j = jt * TK + jq * 4 + e;
            float4 q01 = __ldg(src + j * 2);
            float4 q23 = __ldg(src + j * 2 + 1);
            if ((mw >> (jq * 4 + e)) & 1u) {
                z0 += fmaxf(AC[0].x * q01.x, AC[0].y * q01.y);
                z1 += fmaxf(AC[1].x * q01.z, AC[1].y * q01.w);
                z2 += fmaxf(AC[2].x * q23.x, AC[2].y * q23.y);
                z3 += fmaxf(AC[3].x * q23.z, AC[3].y * q23.w);
            }
        }
    }
    zr[i][0][jq] = z0; zr[i][1][jq] = z1; zr[i][2][jq] = z2; zr[i][3][jq] = z3;
    __syncthreads();

    if (t < 128) {
        const int ii = t >> 2, h = t & 3;
        float Z = 0.f;
#pragma unroll
        for (int g = 0; g < 8; g++) Z += zr[ii][h][g];
        float2 ac  = __ldg(&g_iAC[(b * HH + h) * NN + i0 + ii]);
        float  inv = (Z > 0.f) ? 0.25f / Z : 0.f;
        g_irow[(b * HH + h) * NN + i0 + ii] = make_float2(ac.x * inv, ac.y * inv);
    }
}

// ---------------------------------------------------------------------------
// Kernel 5 (main): P_avg @ Wh via mma.sync tf32, M=32, grid (64,4)=256 CTAs.
// 8 warps; gen role (amt=w>>2, ks=w&3) and consume role (mw=w>>2, nw=w&3).
// ---------------------------------------------------------------------------
// SMEM: Af[2][2mt][4ks][32] uint4 (8K) @0 | Bf[2][4ks][8ntp][32] uint4 (32K) @8192
//     | JP[2][64] float4 (2K) @40960
#define SM_A(p, mt, ks, ln)   ((((p) * 2 + (mt)) * 4 + (ks)) * 32 + (ln))
#define SM_B4(p, ks, ntp, ln) ((((p) * 4 + (ks)) * 8 + (ntp)) * 32 + (ln))
#define OFF_BF 8192
#define OFF_JP 40960
#define SMEM_BYTES 43008

__global__ __launch_bounds__(256, 2) void gat_main_mma(float* __restrict__ out)
{
    extern __shared__ char smem[];
    uint4*  Af  = (uint4*)smem;
    uint4*  Bf  = (uint4*)(smem + OFF_BF);
    float4* JPf = (float4*)(smem + OFF_JP);
    const uint32_t Bf_sa = (uint32_t)__cvta_generic_to_shared(Bf);
    const uint32_t JP_sa = (uint32_t)__cvta_generic_to_shared(JPf);

    const int t    = threadIdx.x;
    const int w    = t >> 5;
    const int lane = t & 31;
    const int mw   = w >> 2;            // 0..1: m16 tile (both roles)
    const int nw   = w & 3;             // consume: 32-col group; gen: ks
    const int b    = blockIdx.y;
    const int i0   = blockIdx.x * 32;

    const int r = lane >> 2;            // 0..7
    const int c = lane & 3;             // 0..3

    const int gia = i0 + mw * 16 + r;   // generator rows (global)
    const int gib = gia + 8;

    float2 RA[4], RB[4];                // prescaled (A', C') per head
#pragma unroll
    for (int h = 0; h < HH; h++) {
        RA[h] = __ldg(&g_irow[(b * HH + h) * NN + gia]);
        RB[h] = __ldg(&g_irow[(b * HH + h) * NN + gib]);
    }
    const uint32_t* mba   = g_adjbits + (size_t)gia * 64;
    const uint32_t* mbb   = g_adjbits + (size_t)gib * 64;
    const uint4*    bbase = g_Bfrag4 + (size_t)b * NT * 1024;
    const float4*   jsrc  = (const float4*)(g_jEFi + (size_t)b * NN * HH);

    float acc[4][4];
#pragma unroll
    for (int n = 0; n < 4; n++)
#pragma unroll
        for (int k = 0; k < 4; k++) acc[n][k] = 0.f;

    auto stage = [&](int jn, int q) {
        const uint4* src = bbase + (size_t)jn * 1024;
        const uint32_t bdst = Bf_sa + (uint32_t)q * 16384u;
#pragma unroll
        for (int k4 = 0; k4 < 4; k4++)
            cp_async16(bdst + (uint32_t)(k4 * 256 + t) * 16u, src + k4 * 256 + t);
        if (t < 64)
            cp_async16(JP_sa + (uint32_t)(q * 64 + t) * 16u, jsrc + jn * 64 + t);
        CP_COMMIT();
    };

    // gen fragment (mt=mw, ks=nw) for tile in buffer p
    auto agen = [&](int p, uint32_t ma, uint32_t mb2) {
        const float4* JP = JPf + p * 64;
        const int jA = nw * 8 + c;
        float4 a01 = JP[jA * 2],       a23 = JP[jA * 2 + 1];
        float4 b01 = JP[(jA + 4) * 2], b23 = JP[(jA + 4) * 2 + 1];

        float vaA = (fmaxf(RA[0].x * a01.x, RA[0].y * a01.y)
                   + fmaxf(RA[1].x * a01.z, RA[1].y * a01.w))
                  + (fmaxf(RA[2].x * a23.x, RA[2].y * a23.y)
                   + fmaxf(RA[3].x * a23.z, RA[3].y * a23.w));
        float vbA = (fmaxf(RB[0].x * a01.x, RB[0].y * a01.y)
                   + fmaxf(RB[1].x * a01.z, RB[1].y * a01.w))
                  + (fmaxf(RB[2].x * a23.x, RB[2].y * a23.y)
                   + fmaxf(RB[3].x * a23.z, RB[3].y * a23.w));
        float vaB = (fmaxf(RA[0].x * b01.x, RA[0].y * b01.y)
                   + fmaxf(RA[1].x * b01.z, RA[1].y * b01.w))
                  + (fmaxf(RA[2].x * b23.x, RA[2].y * b23.y)
                   + fmaxf(RA[3].x * b23.z, RA[3].y * b23.w));
        float vbB = (fmaxf(RB[0].x * b01.x, RB[0].y * b01.y)
                   + fmaxf(RB[1].x * b01.z, RB[1].y * b01.w))
                  + (fmaxf(RB[2].x * b23.x, RB[2].y * b23.y)
                   + fmaxf(RB[3].x * b23.z, RB[3].y * b23.w));

        const int sh = nw * 8 + c;
        vaA = ((ma  >> sh)       & 1u) ? vaA : 0.f;
        vbA = ((mb2 >> sh)       & 1u) ? vbA : 0.f;
        vaB = ((ma  >> (sh + 4)) & 1u) ? vaB : 0.f;
        vbB = ((mb2 >> (sh + 4)) & 1u) ? vbB : 0.f;

        Af[SM_A(p, mw, nw, lane)] =
            make_uint4(f2tf32(vaA), f2tf32(vbA), f2tf32(vaB), f2tf32(vbB));
    };

    auto consume = [&](int p) {
#pragma unroll
        for (int ks = 0; ks < 4; ks++) {
            uint4 a  = Af[SM_A(p, mw, ks, lane)];
            uint4 b0 = Bf[SM_B4(p, ks, nw * 2 + 0, lane)];
            uint4 b1 = Bf[SM_B4(p, ks, nw * 2 + 1, lane)];
            mma_tf32(acc[0][0], acc[0][1], acc[0][2], acc[0][3],
                     a.x, a.y, a.z, a.w, b0.x, b0.y);
            mma_tf32(acc[1][0], acc[1][1], acc[1][2], acc[1][3],
                     a.x, a.y, a.z, a.w, b0.z, b0.w);
            mma_tf32(acc[2][0], acc[2][1], acc[2][2], acc[2][3],
                     a.x, a.y, a.z, a.w, b1.x, b1.y);
            mma_tf32(acc[3][0], acc[3][1], acc[3][2], acc[3][3],
                     a.x, a.y, a.z, a.w, b1.z, b1.w);
        }
    };

    // prologue
    stage(0, 0);
    uint32_t maC = __ldg(mba), mbC = __ldg(mbb);
    CP_WAIT0();
    __syncthreads();

    // pipelined mainloop
    for (int jt = 0; jt < NT; jt++) {
        const int p = jt & 1, q = p ^ 1;

        agen(p, maC, mbC);
        __syncthreads();

        uint32_t maN = 0, mbN = 0;
        if (jt + 1 < NT) {
            stage(jt + 1, q);
            maN = __ldg(mba + jt + 1);
            mbN = __ldg(mbb + jt + 1);
        }

        consume(p);

        if (jt + 1 < NT) CP_WAIT0();
        __syncthreads();
        maC = maN; mbC = mbN;
    }

    // epilogue: accumulators are final pre-ReLU outputs
    const int rowa = i0 + mw * 16 + r;
#pragma unroll
    for (int nt = 0; nt < 4; nt++) {
        const int col = nw * 32 + nt * 8 + c * 2;
        float* op = out + ((size_t)(b * NN + rowa)) * FOUT + col;
        *(float2*)op = make_float2(fmaxf(acc[nt][0], 0.f), fmaxf(acc[nt][1], 0.f));
        *(float2*)(op + 8 * FOUT) = make_float2(fmaxf(acc[nt][2], 0.f),
                                                fmaxf(acc[nt][3], 0.f));
    }
}

// ---------------------------------------------------------------------------
extern "C" void kernel_launch(void* const* d_in, const int* in_sizes, int n_in,
                              void* d_out, int out_size)
{
    const float* h      = (const float*)d_in[0];
    const int*   adj    = (const int*)d_in[1];
    const float* W_w    = (const float*)d_in[2];
    const float* W_b    = (const float*)d_in[3];
    const float* attn_w = (const float*)d_in[4];
    float* out = (float*)d_out;

    adjbits_kernel<<<NN, 64>>>(adj);
    wh2_kernel<<<(Bb * NN) / 32, 256>>>(h, W_w, W_b);
    pack_kernel<<<(Bb * NN) / 8, 256>>>(attn_w);
    bfrag_kernel<<<dim3(NT, Bb), 256>>>();
    zsum_kernel<<<dim3(NN / 32, Bb), 256>>>();

    cudaFuncSetAttribute(gat_main_mma,
                         cudaFuncAttributeMaxDynamicSharedMemorySize, SMEM_BYTES);
    gat_main_mma<<<dim3(NN / 32, Bb), 256, SMEM_BYTES>>>(out);
}

// round 8
// speedup vs baseline: 1.8346x; 1.8346x over previous
#include <cuda_runtime.h>
#include <cstdint>

#define Bb   4
#define NN   2048
#define FIN  256
#define FOUT 128
#define HH   4
#define NEG  0.2f
#define TKI  64          // j per mainloop iteration
#define NI   (NN / TKI)  // 32

// ---------------------------------------------------------------------------
// scratch (no cudaMalloc allowed)
// ---------------------------------------------------------------------------
__device__ float    g_Wh[Bb * NN * FOUT];        // [b][n][o]  4 MB
__device__ float2   g_iAC[Bb * HH * NN];         // (e^el, e^.2el) per (b,h,i)
__device__ float2   g_jEFi[Bb * NN * HH];        // (e^er, e^.2er), [(b*NN+n)*4+h]
__device__ float2   g_irow[Bb * HH * NN];        // prescaled (A*0.25/Z, C*0.25/Z)
__device__ uint32_t g_adjbits[NN * 64];          // 512 KB
__device__ uint4    g_Bfrag4[Bb * (NN / 32) * 1024]; // Wh B-fragments (tf32)

// ---------------------------------------------------------------------------
__device__ __forceinline__ uint32_t f2tf32(float f) {
    uint32_t u;
    asm("cvt.rna.tf32.f32 %0, %1;" : "=r"(u) : "f"(f));
    return u;
}
__device__ __forceinline__ void mma_tf32(float& c0, float& c1, float& c2, float& c3,
                                         uint32_t a0, uint32_t a1, uint32_t a2, uint32_t a3,
                                         uint32_t b0, uint32_t b1) {
    asm volatile("mma.sync.aligned.m16n8k8.row.col.f32.tf32.tf32.f32 "
                 "{%0,%1,%2,%3}, {%4,%5,%6,%7}, {%8,%9}, {%0,%1,%2,%3};"
                 : "+f"(c0), "+f"(c1), "+f"(c2), "+f"(c3)
                 : "r"(a0), "r"(a1), "r"(a2), "r"(a3), "r"(b0), "r"(b1));
}
__device__ __forceinline__ void cp_async16(uint32_t dst, const void* src) {
    asm volatile("cp.async.cg.shared.global [%0], [%1], 16;" :: "r"(dst), "l"(src));
}
#define CP_COMMIT() asm volatile("cp.async.commit_group;" ::: "memory")
#define CP_WAIT0()  asm volatile("cp.async.wait_group 0;" ::: "memory")

// ---------------------------------------------------------------------------
// Kernel 0: adj -> bitmask
// ---------------------------------------------------------------------------
__global__ __launch_bounds__(64) void adjbits_kernel(const int* __restrict__ adj)
{
    const int row = blockIdx.x, w = threadIdx.x;
    const int4* p = (const int4*)(adj + (size_t)row * NN + w * 32);
    uint32_t bits = 0;
#pragma unroll
    for (int q = 0; q < 8; q++) {
        int4 v = __ldg(p + q);
        bits |= (v.x ? 1u : 0u) << (q * 4 + 0);
        bits |= (v.y ? 1u : 0u) << (q * 4 + 1);
        bits |= (v.z ? 1u : 0u) << (q * 4 + 2);
        bits |= (v.w ? 1u : 0u) << (q * 4 + 3);
    }
    g_adjbits[row * 64 + w] = bits;
}

// ---------------------------------------------------------------------------
// Kernel 1: Wh = h @ W^T + b  (register-tiled fp32 GEMM)
// ---------------------------------------------------------------------------
__global__ __launch_bounds__(256) void wh2_kernel(const float* __restrict__ h,
                                                  const float* __restrict__ Ww,
                                                  const float* __restrict__ Wb)
{
    __shared__ float As[32][32];
    __shared__ float Bs[32][128];
    const int t     = threadIdx.x;
    const int grow0 = blockIdx.x * 32;
    const int col   = (t & 31) * 4;
    const int row0  = (t >> 5) * 4;

    float acc[4][4];
#pragma unroll
    for (int r = 0; r < 4; r++)
#pragma unroll
        for (int c = 0; c < 4; c++) acc[r][c] = 0.f;

    for (int kb = 0; kb < FIN; kb += 32) {
        {
            int r = t >> 3, k4 = (t & 7) * 4;
            *(float4*)&As[r][k4] =
                *(const float4*)(h + (size_t)(grow0 + r) * FIN + kb + k4);
        }
        {
            int o = t >> 1, kh = (t & 1) * 16;
#pragma unroll
            for (int s2 = 0; s2 < 4; s2++) {
                float4 v = *(const float4*)(Ww + (size_t)o * FIN + kb + kh + s2 * 4);
                Bs[kh + s2 * 4 + 0][o] = v.x;
                Bs[kh + s2 * 4 + 1][o] = v.y;
                Bs[kh + s2 * 4 + 2][o] = v.z;
                Bs[kh + s2 * 4 + 3][o] = v.w;
            }
        }
        __syncthreads();
#pragma unroll
        for (int k = 0; k < 32; k++) {
            float4 bv = *(const float4*)&Bs[k][col];
            float a0 = As[row0 + 0][k], a1 = As[row0 + 1][k];
            float a2 = As[row0 + 2][k], a3 = As[row0 + 3][k];
            acc[0][0] += a0 * bv.x; acc[0][1] += a0 * bv.y; acc[0][2] += a0 * bv.z; acc[0][3] += a0 * bv.w;
            acc[1][0] += a1 * bv.x; acc[1][1] += a1 * bv.y; acc[1][2] += a1 * bv.z; acc[1][3] += a1 * bv.w;
            acc[2][0] += a2 * bv.x; acc[2][1] += a2 * bv.y; acc[2][2] += a2 * bv.z; acc[2][3] += a2 * bv.w;
            acc[3][0] += a3 * bv.x; acc[3][1] += a3 * bv.y; acc[3][2] += a3 * bv.z; acc[3][3] += a3 * bv.w;
        }
        __syncthreads();
    }

    float4 bias = *(const float4*)(Wb + col);
    const float bc[4] = {bias.x, bias.y, bias.z, bias.w};
#pragma unroll
    for (int r = 0; r < 4; r++) {
        float4 o4 = make_float4(acc[r][0] + bc[0], acc[r][1] + bc[1],
                                acc[r][2] + bc[2], acc[r][3] + bc[3]);
        *(float4*)(g_Wh + (size_t)(grow0 + row0 + r) * FOUT + col) = o4;
    }
}

// ---------------------------------------------------------------------------
// Kernel 2: per (b,h,n): el/er dot products + exps (exact fp32)
// ---------------------------------------------------------------------------
__global__ __launch_bounds__(256) void pack_kernel(const float* __restrict__ attn_w)
{
    const int t    = threadIdx.x;
    const int warp = t >> 5;
    const int lane = t & 31;
    const int row  = blockIdx.x * 8 + warp;
    const int b    = row >> 11;
    const int n    = row & (NN - 1);

    float4 wh = *(const float4*)(g_Wh + (size_t)row * FOUT + lane * 4);
#pragma unroll
    for (int hh = 0; hh < HH; hh++) {
        float4 al = *(const float4*)(attn_w + hh * 2 * FOUT + lane * 4);
        float4 ar = *(const float4*)(attn_w + hh * 2 * FOUT + FOUT + lane * 4);
        float sl = wh.x * al.x + wh.y * al.y + wh.z * al.z + wh.w * al.w;
        float sr = wh.x * ar.x + wh.y * ar.y + wh.z * ar.z + wh.w * ar.w;
#pragma unroll
        for (int off = 16; off > 0; off >>= 1) {
            sl += __shfl_xor_sync(0xffffffffu, sl, off);
            sr += __shfl_xor_sync(0xffffffffu, sr, off);
        }
        if (lane == 0) {
            g_iAC[(b * HH + hh) * NN + n]            = make_float2(expf(sl), expf(NEG * sl));
            g_jEFi[((size_t)(b * NN + n)) * HH + hh] = make_float2(expf(sr), expf(NEG * sr));
        }
    }
}

// ---------------------------------------------------------------------------
// Kernel 3: repack Wh into paired B-fragments (tf32), per 32-j tile.
// ---------------------------------------------------------------------------
__global__ __launch_bounds__(256) void bfrag_kernel()
{
    const int jt = blockIdx.x, b = blockIdx.y, t = threadIdx.x;
    const size_t base = ((size_t)b * (NN / 32) + jt) * 1024;
#pragma unroll
    for (int q = 0; q < 4; q++) {
        const int s    = q * 256 + t;
        const int lane = s & 31;
        const int ntp  = (s >> 5) & 7;
        const int ks   = s >> 8;
        const int j    = jt * 32 + ks * 8 + (lane & 3);
        const int o0   = (ntp * 2) * 8 + (lane >> 2);
        const int o1   = o0 + 8;
        float x = __ldg(&g_Wh[((size_t)(b * NN + j))     * FOUT + o0]);
        float y = __ldg(&g_Wh[((size_t)(b * NN + j + 4)) * FOUT + o0]);
        float z = __ldg(&g_Wh[((size_t)(b * NN + j))     * FOUT + o1]);
        float w = __ldg(&g_Wh[((size_t)(b * NN + j + 4)) * FOUT + o1]);
        g_Bfrag4[base + s] = make_uint4(f2tf32(x), f2tf32(y), f2tf32(z), f2tf32(w));
    }
}

// ---------------------------------------------------------------------------
// Kernel 4: Z pre-pass v2 (smem-tiled j-stream, max-trick).
// grid (64, 4), 256 thr: 32 rows/CTA, thread = (i = t>>3, jq = t&7).
// Writes g_irow = (A*0.25/Z, C*0.25/Z).
// ---------------------------------------------------------------------------
__device__ __forceinline__ uint32_t zswz(uint32_t a) {   // 32B-block XOR swizzle
    return a ^ (((a >> 10) & 7u) << 5);
}
__global__ __launch_bounds__(256) void zsum_kernel()
{
    __shared__ float4 jef[512];           // 8 KB: 256 j x 4 h (float2), swizzled
    __shared__ float  zr[32][4][8];
    const int t  = threadIdx.x;
    const int b  = blockIdx.y;
    const int i0 = blockIdx.x * 32;
    const int i  = t >> 3, jq = t & 7;
    const int gi = i0 + i;

    float2 AC[4];
#pragma unroll
    for (int h = 0; h < HH; h++) AC[h] = __ldg(&g_iAC[(b * HH + h) * NN + gi]);

    float z0 = 0.f, z1 = 0.f, z2 = 0.f, z3 = 0.f;
    const float4*   src4 = (const float4*)(g_jEFi + (size_t)b * NN * HH);
    const uint32_t* mrow = g_adjbits + (size_t)gi * 64;
    char* jefc = (char*)jef;

    for (int c0 = 0; c0 < NN; c0 += 256) {
        __syncthreads();
        {   // stage 256 j (coalesced reads, swizzled writes)
            float4 v0 = __ldg(src4 + (size_t)(c0 + t) * 2);
            float4 v1 = __ldg(src4 + (size_t)(c0 + t) * 2 + 1);
            uint32_t a = zswz((uint32_t)t * 32u);
            *(float4*)(jefc + a)      = v0;
            *(float4*)(jefc + a + 16) = v1;
        }
        __syncthreads();

        const uint32_t mw = __ldg(mrow + (c0 >> 5) + jq);
#pragma unroll 8
        for (int e = 0; e < 32; e++) {
            if ((mw >> e) & 1u) {
                uint32_t a = zswz((uint32_t)(jq * 32 + e) * 32u);
                float4 q01 = *(const float4*)(jefc + a);
                float4 q23 = *(const float4*)(jefc + a + 16);
                z0 += fmaxf(AC[0].x * q01.x, AC[0].y * q01.y);
                z1 += fmaxf(AC[1].x * q01.z, AC[1].y * q01.w);
                z2 += fmaxf(AC[2].x * q23.x, AC[2].y * q23.y);
                z3 += fmaxf(AC[3].x * q23.z, AC[3].y * q23.w);
            }
        }
    }
    __syncthreads();
    zr[i][0][jq] = z0; zr[i][1][jq] = z1; zr[i][2][jq] = z2; zr[i][3][jq] = z3;
    __syncthreads();

    if (t < 128) {
        const int ii = t >> 2, h = t & 3;
        float Z = 0.f;
#pragma unroll
        for (int g = 0; g < 8; g++) Z += zr[ii][h][g];
        float2 ac  = __ldg(&g_iAC[(b * HH + h) * NN + i0 + ii]);
        float  inv = (Z > 0.f) ? 0.25f / Z : 0.f;
        g_irow[(b * HH + h) * NN + i0 + ii] = make_float2(ac.x * inv, ac.y * inv);
    }
}

// ---------------------------------------------------------------------------
// Kernel 5 (main): P_avg @ Wh via mma.sync tf32, M=32, TK=64/iter.
// grid (64,4)=256 CTAs, 8 warps. Gen role (mtg=w>>2, ks=(w&3)*2+kk);
// consume role (mw=w>>2, nw=w&3), 32 MMA/warp/iter.
// ---------------------------------------------------------------------------
// SMEM: Af[2][2mt][8ks][32] uint4 (16K) @0 | Bf[2][2048] uint4 (64K) @16384
//     | JP[2][128] float4 (4K) @81920
#define SM_A(p, mt, ks, ln) ((p) * 512 + ((mt) * 8 + (ks)) * 32 + (ln))
#define SM_B(p, ks, ntp, ln) \
    ((p) * 2048 + ((ks) >> 2) * 1024 + ((ks) & 3) * 256 + (ntp) * 32 + (ln))
#define OFF_BF 16384
#define OFF_JP 81920
#define SMEM_BYTES 86016

__global__ __launch_bounds__(256, 2) void gat_main_mma(float* __restrict__ out)
{
    extern __shared__ char smem[];
    uint4*  Af  = (uint4*)smem;
    uint4*  Bf  = (uint4*)(smem + OFF_BF);
    float4* JPf = (float4*)(smem + OFF_JP);
    const uint32_t Bf_sa = (uint32_t)__cvta_generic_to_shared(Bf);
    const uint32_t JP_sa = (uint32_t)__cvta_generic_to_shared(JPf);

    const int t    = threadIdx.x;
    const int w    = t >> 5;
    const int lane = t & 31;
    const int mw   = w >> 2;            // m16 tile (gen + consume)
    const int nw   = w & 3;             // consume: 32-col group; gen: ks pair
    const int b    = blockIdx.y;
    const int i0   = blockIdx.x * 32;

    const int r = lane >> 2;            // 0..7
    const int c = lane & 3;             // 0..3

    const int gia = i0 + mw * 16 + r;
    const int gib = gia + 8;

    float2 RA[4], RB[4];                // prescaled (A', C') per head
#pragma unroll
    for (int h = 0; h < HH; h++) {
        RA[h] = __ldg(&g_irow[(b * HH + h) * NN + gia]);
        RB[h] = __ldg(&g_irow[(b * HH + h) * NN + gib]);
    }
    const uint32_t* mba   = g_adjbits + (size_t)gia * 64;
    const uint32_t* mbb   = g_adjbits + (size_t)gib * 64;
    const uint4*    bbase = g_Bfrag4 + (size_t)b * (NN / 32) * 1024;
    const float4*   jsrc  = (const float4*)(g_jEFi + (size_t)b * NN * HH);

    float acc[4][4];
#pragma unroll
    for (int n = 0; n < 4; n++)
#pragma unroll
        for (int k = 0; k < 4; k++) acc[n][k] = 0.f;

    auto stage = [&](int jn, int q) {
        const uint4* src = bbase + (size_t)jn * 2048;
        const uint32_t bdst = Bf_sa + (uint32_t)q * 32768u;
#pragma unroll
        for (int k4 = 0; k4 < 8; k4++)
            cp_async16(bdst + (uint32_t)(k4 * 256 + t) * 16u, src + k4 * 256 + t);
        if (t < 128)
            cp_async16(JP_sa + (uint32_t)(q * 128 + t) * 16u, jsrc + jn * 128 + t);
        CP_COMMIT();
    };

    // gen two fragments (mt=mw, ks=nw*2+kk) from JP[p]
    auto agen = [&](int p, uint32_t ma0, uint32_t ma1, uint32_t mb0, uint32_t mb1) {
        const float4* JP = JPf + p * 128;
#pragma unroll
        for (int kk = 0; kk < 2; kk++) {
            const int ks = nw * 2 + kk;
            const int jA = ks * 8 + c;
            float4 a01 = JP[jA * 2],       a23 = JP[jA * 2 + 1];
            float4 b01 = JP[(jA + 4) * 2], b23 = JP[(jA + 4) * 2 + 1];

            float vaA = (fmaxf(RA[0].x * a01.x, RA[0].y * a01.y)
                       + fmaxf(RA[1].x * a01.z, RA[1].y * a01.w))
                      + (fmaxf(RA[2].x * a23.x, RA[2].y * a23.y)
                       + fmaxf(RA[3].x * a23.z, RA[3].y * a23.w));
            float vbA = (fmaxf(RB[0].x * a01.x, RB[0].y * a01.y)
                       + fmaxf(RB[1].x * a01.z, RB[1].y * a01.w))
                      + (fmaxf(RB[2].x * a23.x, RB[2].y * a23.y)
                       + fmaxf(RB[3].x * a23.z, RB[3].y * a23.w));
            float vaB = (fmaxf(RA[0].x * b01.x, RA[0].y * b01.y)
                       + fmaxf(RA[1].x * b01.z, RA[1].y * b01.w))
                      + (fmaxf(RA[2].x * b23.x, RA[2].y * b23.y)
                       + fmaxf(RA[3].x * b23.z, RA[3].y * b23.w));
            float vbB = (fmaxf(RB[0].x * b01.x, RB[0].y * b01.y)
                       + fmaxf(RB[1].x * b01.z, RB[1].y * b01.w))
                      + (fmaxf(RB[2].x * b23.x, RB[2].y * b23.y)
                       + fmaxf(RB[3].x * b23.z, RB[3].y * b23.w));

            const uint32_t mwa = (ks >= 4) ? ma1 : ma0;
            const uint32_t mwb = (ks >= 4) ? mb1 : mb0;
            const int sh = (ks & 3) * 8 + c;
            vaA = ((mwa >> sh)       & 1u) ? vaA : 0.f;
            vbA = ((mwb >> sh)       & 1u) ? vbA : 0.f;
            vaB = ((mwa >> (sh + 4)) & 1u) ? vaB : 0.f;
            vbB = ((mwb >> (sh + 4)) & 1u) ? vbB : 0.f;

            Af[SM_A(p, mw, ks, lane)] =
                make_uint4(f2tf32(vaA), f2tf32(vbA), f2tf32(vaB), f2tf32(vbB));
        }
    };

    auto consume = [&](int p) {
#pragma unroll
        for (int ks = 0; ks < 8; ks++) {
            uint4 a  = Af[SM_A(p, mw, ks, lane)];
            uint4 b0 = Bf[SM_B(p, ks, nw * 2 + 0, lane)];
            uint4 b1 = Bf[SM_B(p, ks, nw * 2 + 1, lane)];
            mma_tf32(acc[0][0], acc[0][1], acc[0][2], acc[0][3],
                     a.x, a.y, a.z, a.w, b0.x, b0.y);
            mma_tf32(acc[1][0], acc[1][1], acc[1][2], acc[1][3],
                     a.x, a.y, a.z, a.w, b0.z, b0.w);
            mma_tf32(acc[2][0], acc[2][1], acc[2][2], acc[2][3],
                     a.x, a.y, a.z, a.w, b1.x, b1.y);
            mma_tf32(acc[3][0], acc[3][1], acc[3][2], acc[3][3],
                     a.x, a.y, a.z, a.w, b1.z, b1.w);
        }
    };

    // prologue: stage iteration 0
    stage(0, 0);
    uint32_t ma0 = __ldg(mba + 0), ma1 = __ldg(mba + 1);
    uint32_t mb0 = __ldg(mbb + 0), mb1 = __ldg(mbb + 1);
    CP_WAIT0();
    __syncthreads();

    // pipelined mainloop: stage(jt+1) first => cover = agen + consume
    for (int jt = 0; jt < NI; jt++) {
        const int p = jt & 1, q = p ^ 1;

        if (jt + 1 < NI) stage(jt + 1, q);

        agen(p, ma0, ma1, mb0, mb1);
        __syncthreads();                 // Af[p] visible

        consume(p);

        if (jt + 1 < NI) {
            ma0 = __ldg(mba + (jt + 1) * 2); ma1 = __ldg(mba + (jt + 1) * 2 + 1);
            mb0 = __ldg(mbb + (jt + 1) * 2); mb1 = __ldg(mbb + (jt + 1) * 2 + 1);
            CP_WAIT0();
        }
        __syncthreads();                 // buffer q ready / Af[p] free
    }

    // epilogue: accumulators are final pre-ReLU outputs
    const int rowa = i0 + mw * 16 + r;
#pragma unroll
    for (int nt = 0; nt < 4; nt++) {
        const int col = nw * 32 + nt * 8 + c * 2;
        float* op = out + ((size_t)(b * NN + rowa)) * FOUT + col;
        *(float2*)op = make_float2(fmaxf(acc[nt][0], 0.f), fmaxf(acc[nt][1], 0.f));
        *(float2*)(op + 8 * FOUT) = make_float2(fmaxf(acc[nt][2], 0.f),
                                                fmaxf(acc[nt][3], 0.f));
    }
}

// ---------------------------------------------------------------------------
extern "C" void kernel_launch(void* const* d_in, const int* in_sizes, int n_in,
                              void* d_out, int out_size)
{
    const float* h      = (const float*)d_in[0];
    const int*   adj    = (const int*)d_in[1];
    const float* W_w    = (const float*)d_in[2];
    const float* W_b    = (const float*)d_in[3];
    const float* attn_w = (const float*)d_in[4];
    float* out = (float*)d_out;

    adjbits_kernel<<<NN, 64>>>(adj);
    wh2_kernel<<<(Bb * NN) / 32, 256>>>(h, W_w, W_b);
    pack_kernel<<<(Bb * NN) / 8, 256>>>(attn_w);
    bfrag_kernel<<<dim3(NN / 32, Bb), 256>>>();
    zsum_kernel<<<dim3(NN / 32, Bb), 256>>>();

    cudaFuncSetAttribute(gat_main_mma,
                         cudaFuncAttributeMaxDynamicSharedMemorySize, SMEM_BYTES);
    gat_main_mma<<<dim3(NN / 32, Bb), 256, SMEM_BYTES>>>(out);
}

// round 9
// speedup vs baseline: 1.8360x; 1.0008x over previous
#include <cuda_runtime.h>
#include <cstdint>

#define Bb   4
#define NN   2048
#define FIN  256
#define FOUT 128
#define HH   4
#define NEG  0.2f
#define TKI  64          // j per mainloop iteration
#define NI   (NN / TKI)  // 32

// ---------------------------------------------------------------------------
// scratch (no cudaMalloc allowed)
// ---------------------------------------------------------------------------
__device__ float2   g_iAC[Bb * HH * NN];         // (e^el, e^.2el) per (b,h,i)
__device__ float2   g_jEFi[Bb * NN * HH];        // (e^er, e^.2er), [(b*NN+n)*4+h]
__device__ float2   g_irow[Bb * HH * NN];        // prescaled (A*0.25/Z, C*0.25/Z)
__device__ uint32_t g_adjbits[NN * 64];          // 512 KB
__device__ uint4    g_Bfrag4[Bb * (NN / 32) * 1024]; // Wh B-fragments (tf32)

// ---------------------------------------------------------------------------
__device__ __forceinline__ uint32_t f2tf32(float f) {
    uint32_t u;
    asm("cvt.rna.tf32.f32 %0, %1;" : "=r"(u) : "f"(f));
    return u;
}
__device__ __forceinline__ void mma_tf32(float& c0, float& c1, float& c2, float& c3,
                                         uint32_t a0, uint32_t a1, uint32_t a2, uint32_t a3,
                                         uint32_t b0, uint32_t b1) {
    asm volatile("mma.sync.aligned.m16n8k8.row.col.f32.tf32.tf32.f32 "
                 "{%0,%1,%2,%3}, {%4,%5,%6,%7}, {%8,%9}, {%0,%1,%2,%3};"
                 : "+f"(c0), "+f"(c1), "+f"(c2), "+f"(c3)
                 : "r"(a0), "r"(a1), "r"(a2), "r"(a3), "r"(b0), "r"(b1));
}
__device__ __forceinline__ void cp_async16(uint32_t dst, const void* src) {
    asm volatile("cp.async.cg.shared.global [%0], [%1], 16;" :: "r"(dst), "l"(src));
}
#define CP_COMMIT() asm volatile("cp.async.commit_group;" ::: "memory")
#define CP_WAIT0()  asm volatile("cp.async.wait_group 0;" ::: "memory")

// ---------------------------------------------------------------------------
// Kernel 0: adj -> bitmask
// ---------------------------------------------------------------------------
__global__ __launch_bounds__(64) void adjbits_kernel(const int* __restrict__ adj)
{
    const int row = blockIdx.x, w = threadIdx.x;
    const int4* p = (const int4*)(adj + (size_t)row * NN + w * 32);
    uint32_t bits = 0;
#pragma unroll
    for (int q = 0; q < 8; q++) {
        int4 v = __ldg(p + q);
        bits |= (v.x ? 1u : 0u) << (q * 4 + 0);
        bits |= (v.y ? 1u : 0u) << (q * 4 + 1);
        bits |= (v.z ? 1u : 0u) << (q * 4 + 2);
        bits |= (v.w ? 1u : 0u) << (q * 4 + 3);
    }
    g_adjbits[row * 64 + w] = bits;
}

// ---------------------------------------------------------------------------
// Kernel 1 (fused): Wh tile GEMM + B-fragment emit + el/er exps.
// Block = 32 rows x 128 cols (grid 256, 256 thr). No g_Wh global.
// ---------------------------------------------------------------------------
__global__ __launch_bounds__(256) void wh_fused(const float* __restrict__ hsrc,
                                                const float* __restrict__ Ww,
                                                const float* __restrict__ Wb,
                                                const float* __restrict__ attn_w)
{
    __shared__ float Bs[32][128];    // Ww^T slab (per kb)
    __shared__ float Whs[32][128];   // output tile
    const int t     = threadIdx.x;
    const int grow0 = blockIdx.x * 32;
    const int col   = (t & 31) * 4;
    const int rl0   = (t >> 5) * 4;  // local row base for GEMM

    float acc[4][4];
#pragma unroll
    for (int r = 0; r < 4; r++)
#pragma unroll
        for (int c = 0; c < 4; c++) acc[r][c] = 0.f;

    const float* hr0 = hsrc + (size_t)(grow0 + rl0 + 0) * FIN;
    const float* hr1 = hsrc + (size_t)(grow0 + rl0 + 1) * FIN;
    const float* hr2 = hsrc + (size_t)(grow0 + rl0 + 2) * FIN;
    const float* hr3 = hsrc + (size_t)(grow0 + rl0 + 3) * FIN;

    for (int kb = 0; kb < FIN; kb += 32) {
        {   // stage Bs = Ww^T slab
            int o = t >> 1, kh = (t & 1) * 16;
#pragma unroll
            for (int s2 = 0; s2 < 4; s2++) {
                float4 v = __ldg((const float4*)(Ww + (size_t)o * FIN + kb + kh + s2 * 4));
                Bs[kh + s2 * 4 + 0][o] = v.x;
                Bs[kh + s2 * 4 + 1][o] = v.y;
                Bs[kh + s2 * 4 + 2][o] = v.z;
                Bs[kh + s2 * 4 + 3][o] = v.w;
            }
        }
        __syncthreads();
#pragma unroll
        for (int k4 = 0; k4 < 32; k4 += 4) {
            float4 a0 = __ldg((const float4*)(hr0 + kb + k4));
            float4 a1 = __ldg((const float4*)(hr1 + kb + k4));
            float4 a2 = __ldg((const float4*)(hr2 + kb + k4));
            float4 a3 = __ldg((const float4*)(hr3 + kb + k4));
            float4 b0 = *(const float4*)&Bs[k4 + 0][col];
            float4 b1 = *(const float4*)&Bs[k4 + 1][col];
            float4 b2 = *(const float4*)&Bs[k4 + 2][col];
            float4 b3 = *(const float4*)&Bs[k4 + 3][col];
#define FMA4(ar, bv) \
            acc[0][0] += a0.ar * bv.x; acc[0][1] += a0.ar * bv.y; \
            acc[0][2] += a0.ar * bv.z; acc[0][3] += a0.ar * bv.w; \
            acc[1][0] += a1.ar * bv.x; acc[1][1] += a1.ar * bv.y; \
            acc[1][2] += a1.ar * bv.z; acc[1][3] += a1.ar * bv.w; \
            acc[2][0] += a2.ar * bv.x; acc[2][1] += a2.ar * bv.y; \
            acc[2][2] += a2.ar * bv.z; acc[2][3] += a2.ar * bv.w; \
            acc[3][0] += a3.ar * bv.x; acc[3][1] += a3.ar * bv.y; \
            acc[3][2] += a3.ar * bv.z; acc[3][3] += a3.ar * bv.w;
            FMA4(x, b0) FMA4(y, b1) FMA4(z, b2) FMA4(w, b3)
#undef FMA4
        }
        __syncthreads();
    }

    // add bias, stage tile to smem
    {
        float4 bias = __ldg((const float4*)(Wb + col));
#pragma unroll
        for (int r = 0; r < 4; r++) {
            float4 o4 = make_float4(acc[r][0] + bias.x, acc[r][1] + bias.y,
                                    acc[r][2] + bias.z, acc[r][3] + bias.w);
            *(float4*)&Whs[rl0 + r][col] = o4;
        }
    }
    __syncthreads();

    const int b  = grow0 >> 11;
    const int n0 = grow0 & (NN - 1);

    // (a) emit B-fragments (tf32) straight from smem
    {
        const size_t base = ((size_t)b * (NN / 32) + (n0 >> 5)) * 1024;
#pragma unroll
        for (int q = 0; q < 4; q++) {
            const int s    = q * 256 + t;
            const int lane = s & 31;
            const int ntp  = (s >> 5) & 7;
            const int ks   = s >> 8;
            const int jl   = ks * 8 + (lane & 3);
            const int o0   = ntp * 16 + (lane >> 2);
            g_Bfrag4[base + s] = make_uint4(f2tf32(Whs[jl][o0]),
                                            f2tf32(Whs[jl + 4][o0]),
                                            f2tf32(Whs[jl][o0 + 8]),
                                            f2tf32(Whs[jl + 4][o0 + 8]));
        }
    }

    // (b) el/er dots + exps (exact fp32)
    {
        const int w    = t >> 5;
        const int lane = t & 31;
        float4 al[HH], ar[HH];
#pragma unroll
        for (int hh = 0; hh < HH; hh++) {
            al[hh] = __ldg((const float4*)(attn_w + hh * 2 * FOUT + lane * 4));
            ar[hh] = __ldg((const float4*)(attn_w + hh * 2 * FOUT + FOUT + lane * 4));
        }
#pragma unroll
        for (int r = 0; r < 4; r++) {
            const int rowl = w * 4 + r;
            const int n    = n0 + rowl;
            float4 v = *(const float4*)&Whs[rowl][lane * 4];
#pragma unroll
            for (int hh = 0; hh < HH; hh++) {
                float sl = v.x * al[hh].x + v.y * al[hh].y
                         + v.z * al[hh].z + v.w * al[hh].w;
                float sr = v.x * ar[hh].x + v.y * ar[hh].y
                         + v.z * ar[hh].z + v.w * ar[hh].w;
#pragma unroll
                for (int off = 16; off > 0; off >>= 1) {
                    sl += __shfl_xor_sync(0xffffffffu, sl, off);
                    sr += __shfl_xor_sync(0xffffffffu, sr, off);
                }
                if (lane == 0) {
                    g_iAC[(b * HH + hh) * NN + n] =
                        make_float2(expf(sl), expf(NEG * sl));
                    g_jEFi[((size_t)(b * NN + n)) * HH + hh] =
                        make_float2(expf(sr), expf(NEG * sr));
                }
            }
        }
    }
}

// ---------------------------------------------------------------------------
// Kernel 2: Z pre-pass (smem-tiled j-stream, max-trick).
// ---------------------------------------------------------------------------
__device__ __forceinline__ uint32_t zswz(uint32_t a) {   // 32B-block XOR swizzle
    return a ^ (((a >> 10) & 7u) << 5);
}
__global__ __launch_bounds__(256) void zsum_kernel()
{
    __shared__ float4 jef[512];           // 8 KB
    __shared__ float  zr[32][4][8];
    const int t  = threadIdx.x;
    const int b  = blockIdx.y;
    const int i0 = blockIdx.x * 32;
    const int i  = t >> 3, jq = t & 7;
    const int gi = i0 + i;

    float2 AC[4];
#pragma unroll
    for (int h = 0; h < HH; h++) AC[h] = __ldg(&g_iAC[(b * HH + h) * NN + gi]);

    float z0 = 0.f, z1 = 0.f, z2 = 0.f, z3 = 0.f;
    const float4*   src4 = (const float4*)(g_jEFi + (size_t)b * NN * HH);
    const uint32_t* mrow = g_adjbits + (size_t)gi * 64;
    char* jefc = (char*)jef;

    for (int c0 = 0; c0 < NN; c0 += 256) {
        __syncthreads();
        {
            float4 v0 = __ldg(src4 + (size_t)(c0 + t) * 2);
            float4 v1 = __ldg(src4 + (size_t)(c0 + t) * 2 + 1);
            uint32_t a = zswz((uint32_t)t * 32u);
            *(float4*)(jefc + a)      = v0;
            *(float4*)(jefc + a + 16) = v1;
        }
        __syncthreads();

        const uint32_t mw = __ldg(mrow + (c0 >> 5) + jq);
#pragma unroll 8
        for (int e = 0; e < 32; e++) {
            if ((mw >> e) & 1u) {
                uint32_t a = zswz((uint32_t)(jq * 32 + e) * 32u);
                float4 q01 = *(const float4*)(jefc + a);
                float4 q23 = *(const float4*)(jefc + a + 16);
                z0 += fmaxf(AC[0].x * q01.x, AC[0].y * q01.y);
                z1 += fmaxf(AC[1].x * q01.z, AC[1].y * q01.w);
                z2 += fmaxf(AC[2].x * q23.x, AC[2].y * q23.y);
                z3 += fmaxf(AC[3].x * q23.z, AC[3].y * q23.w);
            }
        }
    }
    __syncthreads();
    zr[i][0][jq] = z0; zr[i][1][jq] = z1; zr[i][2][jq] = z2; zr[i][3][jq] = z3;
    __syncthreads();

    if (t < 128) {
        const int ii = t >> 2, h = t & 3;
        float Z = 0.f;
#pragma unroll
        for (int g = 0; g < 8; g++) Z += zr[ii][h][g];
        float2 ac  = __ldg(&g_iAC[(b * HH + h) * NN + i0 + ii]);
        float  inv = (Z > 0.f) ? 0.25f / Z : 0.f;
        g_irow[(b * HH + h) * NN + i0 + ii] = make_float2(ac.x * inv, ac.y * inv);
    }
}

// ---------------------------------------------------------------------------
// Kernel 3 (main): P_avg @ Wh via mma.sync tf32, M=32, TK=64/iter.
// ---------------------------------------------------------------------------
#define SM_A(p, mt, ks, ln) ((p) * 512 + ((mt) * 8 + (ks)) * 32 + (ln))
#define SM_B(p, ks, ntp, ln) \
    ((p) * 2048 + ((ks) >> 2) * 1024 + ((ks) & 3) * 256 + (ntp) * 32 + (ln))
#define OFF_BF 16384
#define OFF_JP 81920
#define SMEM_BYTES 86016

__global__ __launch_bounds__(256, 2) void gat_main_mma(float* __restrict__ out)
{
    extern __shared__ char smem[];
    uint4*  Af  = (uint4*)smem;
    uint4*  Bf  = (uint4*)(smem + OFF_BF);
    float4* JPf = (float4*)(smem + OFF_JP);
    const uint32_t Bf_sa = (uint32_t)__cvta_generic_to_shared(Bf);
    const uint32_t JP_sa = (uint32_t)__cvta_generic_to_shared(JPf);

    const int t    = threadIdx.x;
    const int w    = t >> 5;
    const int lane = t & 31;
    const int mw   = w >> 2;
    const int nw   = w & 3;
    const int b    = blockIdx.y;
    const int i0   = blockIdx.x * 32;

    const int r = lane >> 2;
    const int c = lane & 3;

    const int gia = i0 + mw * 16 + r;
    const int gib = gia + 8;

    float2 RA[4], RB[4];
#pragma unroll
    for (int h = 0; h < HH; h++) {
        RA[h] = __ldg(&g_irow[(b * HH + h) * NN + gia]);
        RB[h] = __ldg(&g_irow[(b * HH + h) * NN + gib]);
    }
    const uint32_t* mba   = g_adjbits + (size_t)gia * 64;
    const uint32_t* mbb   = g_adjbits + (size_t)gib * 64;
    const uint4*    bbase = g_Bfrag4 + (size_t)b * (NN / 32) * 1024;
    const float4*   jsrc  = (const float4*)(g_jEFi + (size_t)b * NN * HH);

    float acc[4][4];
#pragma unroll
    for (int n = 0; n < 4; n++)
#pragma unroll
        for (int k = 0; k < 4; k++) acc[n][k] = 0.f;

    auto stage = [&](int jn, int q) {
        const uint4* src = bbase + (size_t)jn * 2048;
        const uint32_t bdst = Bf_sa + (uint32_t)q * 32768u;
#pragma unroll
        for (int k4 = 0; k4 < 8; k4++)
            cp_async16(bdst + (uint32_t)(k4 * 256 + t) * 16u, src + k4 * 256 + t);
        if (t < 128)
            cp_async16(JP_sa + (uint32_t)(q * 128 + t) * 16u, jsrc + jn * 128 + t);
        CP_COMMIT();
    };

    auto agen = [&](int p, uint32_t ma0, uint32_t ma1, uint32_t mb0, uint32_t mb1) {
        const float4* JP = JPf + p * 128;
#pragma unroll
        for (int kk = 0; kk < 2; kk++) {
            const int ks = nw * 2 + kk;
            const int jA = ks * 8 + c;
            float4 a01 = JP[jA * 2],       a23 = JP[jA * 2 + 1];
            float4 b01 = JP[(jA + 4) * 2], b23 = JP[(jA + 4) * 2 + 1];

            float vaA = (fmaxf(RA[0].x * a01.x, RA[0].y * a01.y)
                       + fmaxf(RA[1].x * a01.z, RA[1].y * a01.w))
                      + (fmaxf(RA[2].x * a23.x, RA[2].y * a23.y)
                       + fmaxf(RA[3].x * a23.z, RA[3].y * a23.w));
            float vbA = (fmaxf(RB[0].x * a01.x, RB[0].y * a01.y)
                       + fmaxf(RB[1].x * a01.z, RB[1].y * a01.w))
                      + (fmaxf(RB[2].x * a23.x, RB[2].y * a23.y)
                       + fmaxf(RB[3].x * a23.z, RB[3].y * a23.w));
            float vaB = (fmaxf(RA[0].x * b01.x, RA[0].y * b01.y)
                       + fmaxf(RA[1].x * b01.z, RA[1].y * b01.w))
                      + (fmaxf(RA[2].x * b23.x, RA[2].y * b23.y)
                       + fmaxf(RA[3].x * b23.z, RA[3].y * b23.w));
            float vbB = (fmaxf(RB[0].x * b01.x, RB[0].y * b01.y)
                       + fmaxf(RB[1].x * b01.z, RB[1].y * b01.w))
                      + (fmaxf(RB[2].x * b23.x, RB[2].y * b23.y)
                       + fmaxf(RB[3].x * b23.z, RB[3].y * b23.w));

            const uint32_t mwa = (ks >= 4) ? ma1 : ma0;
            const uint32_t mwb = (ks >= 4) ? mb1 : mb0;
            const int sh = (ks & 3) * 8 + c;
            vaA = ((mwa >> sh)       & 1u) ? vaA : 0.f;
            vbA = ((mwb >> sh)       & 1u) ? vbA : 0.f;
            vaB = ((mwa >> (sh + 4)) & 1u) ? vaB : 0.f;
            vbB = ((mwb >> (sh + 4)) & 1u) ? vbB : 0.f;

            Af[SM_A(p, mw, ks, lane)] =
                make_uint4(f2tf32(vaA), f2tf32(vbA), f2tf32(vaB), f2tf32(vbB));
        }
    };

    auto consume = [&](int p) {
#pragma unroll
        for (int ks = 0; ks < 8; ks++) {
            uint4 a  = Af[SM_A(p, mw, ks, lane)];
            uint4 b0 = Bf[SM_B(p, ks, nw * 2 + 0, lane)];
            uint4 b1 = Bf[SM_B(p, ks, nw * 2 + 1, lane)];
            mma_tf32(acc[0][0], acc[0][1], acc[0][2], acc[0][3],
                     a.x, a.y, a.z, a.w, b0.x, b0.y);
            mma_tf32(acc[1][0], acc[1][1], acc[1][2], acc[1][3],
                     a.x, a.y, a.z, a.w, b0.z, b0.w);
            mma_tf32(acc[2][0], acc[2][1], acc[2][2], acc[2][3],
                     a.x, a.y, a.z, a.w, b1.x, b1.y);
            mma_tf32(acc[3][0], acc[3][1], acc[3][2], acc[3][3],
                     a.x, a.y, a.z, a.w, b1.z, b1.w);
        }
    };

    stage(0, 0);
    uint32_t ma0 = __ldg(mba + 0), ma1 = __ldg(mba + 1);
    uint32_t mb0 = __ldg(mbb + 0), mb1 = __ldg(mbb + 1);
    CP_WAIT0();
    __syncthreads();

    for (int jt = 0; jt < NI; jt++) {
        const int p = jt & 1, q = p ^ 1;

        if (jt + 1 < NI) stage(jt + 1, q);

        agen(p, ma0, ma1, mb0, mb1);
        __syncthreads();

        consume(p);

        if (jt + 1 < NI) {
            ma0 = __ldg(mba + (jt + 1) * 2); ma1 = __ldg(mba + (jt + 1) * 2 + 1);
            mb0 = __ldg(mbb + (jt + 1) * 2); mb1 = __ldg(mbb + (jt + 1) * 2 + 1);
            CP_WAIT0();
        }
        __syncthreads();
    }

    const int rowa = i0 + mw * 16 + r;
#pragma unroll
    for (int nt = 0; nt < 4; nt++) {
        const int col = nw * 32 + nt * 8 + c * 2;
        float* op = out + ((size_t)(b * NN + rowa)) * FOUT + col;
        *(float2*)op = make_float2(fmaxf(acc[nt][0], 0.f), fmaxf(acc[nt][1], 0.f));
        *(float2*)(op + 8 * FOUT) = make_float2(fmaxf(acc[nt][2], 0.f),
                                                fmaxf(acc[nt][3], 0.f));
    }
}

// ---------------------------------------------------------------------------
extern "C" void kernel_launch(void* const* d_in, const int* in_sizes, int n_in,
                              void* d_out, int out_size)
{
    const float* h      = (const float*)d_in[0];
    const int*   adj    = (const int*)d_in[1];
    const float* W_w    = (const float*)d_in[2];
    const float* W_b    = (const float*)d_in[3];
    const float* attn_w = (const float*)d_in[4];
    float* out = (float*)d_out;

    adjbits_kernel<<<NN, 64>>>(adj);
    wh_fused<<<(Bb * NN) / 32, 256>>>(h, W_w, W_b, attn_w);
    zsum_kernel<<<dim3(NN / 32, Bb), 256>>>();

    cudaFuncSetAttribute(gat_main_mma,
                         cudaFuncAttributeMaxDynamicSharedMemorySize, SMEM_BYTES);
    gat_main_mma<<<dim3(NN / 32, Bb), 256, SMEM_BYTES>>>(out);
}

// round 10
// speedup vs baseline: 1.8622x; 1.0143x over previous
#include <cuda_runtime.h>
#include <cstdint>

#define Bb   4
#define NN   2048
#define FIN  256
#define FOUT 128
#define HH   4
#define NEG  0.2f
#define TKI  32          // j per mainloop iteration
#define NI   (NN / TKI)  // 64

// ---------------------------------------------------------------------------
// scratch (no cudaMalloc allowed)
// ---------------------------------------------------------------------------
__device__ float2   g_iAC[Bb * HH * NN];         // (e^el, e^.2el) per (b,h,i)
__device__ float2   g_jEFi[Bb * NN * HH];        // (e^er, e^.2er), [(b*NN+n)*4+h]
__device__ float2   g_irow[Bb * HH * NN];        // prescaled (A*0.25/Z, C*0.25/Z)
__device__ uint32_t g_adjbits[NN * 64];          // 512 KB
__device__ uint4    g_Bfrag4[Bb * (NN / 32) * 1024]; // Wh B-fragments (tf32)

// ---------------------------------------------------------------------------
__device__ __forceinline__ uint32_t f2tf32(float f) {
    uint32_t u;
    asm("cvt.rna.tf32.f32 %0, %1;" : "=r"(u) : "f"(f));
    return u;
}
__device__ __forceinline__ void mma_tf32(float& c0, float& c1, float& c2, float& c3,
                                         uint32_t a0, uint32_t a1, uint32_t a2, uint32_t a3,
                                         uint32_t b0, uint32_t b1) {
    asm volatile("mma.sync.aligned.m16n8k8.row.col.f32.tf32.tf32.f32 "
                 "{%0,%1,%2,%3}, {%4,%5,%6,%7}, {%8,%9}, {%0,%1,%2,%3};"
                 : "+f"(c0), "+f"(c1), "+f"(c2), "+f"(c3)
                 : "r"(a0), "r"(a1), "r"(a2), "r"(a3), "r"(b0), "r"(b1));
}
__device__ __forceinline__ void cp_async16(uint32_t dst, const void* src) {
    asm volatile("cp.async.cg.shared.global [%0], [%1], 16;" :: "r"(dst), "l"(src));
}
#define CP_COMMIT() asm volatile("cp.async.commit_group;" ::: "memory")
#define CP_WAIT0()  asm volatile("cp.async.wait_group 0;" ::: "memory")

// ---------------------------------------------------------------------------
// Kernel 0: adj -> bitmask
// ---------------------------------------------------------------------------
__global__ __launch_bounds__(64) void adjbits_kernel(const int* __restrict__ adj)
{
    const int row = blockIdx.x, w = threadIdx.x;
    const int4* p = (const int4*)(adj + (size_t)row * NN + w * 32);
    uint32_t bits = 0;
#pragma unroll
    for (int q = 0; q < 8; q++) {
        int4 v = __ldg(p + q);
        bits |= (v.x ? 1u : 0u) << (q * 4 + 0);
        bits |= (v.y ? 1u : 0u) << (q * 4 + 1);
        bits |= (v.z ? 1u : 0u) << (q * 4 + 2);
        bits |= (v.w ? 1u : 0u) << (q * 4 + 3);
    }
    g_adjbits[row * 64 + w] = bits;
}

// ---------------------------------------------------------------------------
// Kernel 1 (fused): Wh tile GEMM + B-fragment emit + el/er exps.
// ---------------------------------------------------------------------------
__global__ __launch_bounds__(256) void wh_fused(const float* __restrict__ hsrc,
                                                const float* __restrict__ Ww,
                                                const float* __restrict__ Wb,
                                                const float* __restrict__ attn_w)
{
    __shared__ float Bs[32][128];    // Ww^T slab (per kb)
    __shared__ float Whs[32][128];   // output tile
    const int t     = threadIdx.x;
    const int grow0 = blockIdx.x * 32;
    const int col   = (t & 31) * 4;
    const int rl0   = (t >> 5) * 4;

    float acc[4][4];
#pragma unroll
    for (int r = 0; r < 4; r++)
#pragma unroll
        for (int c = 0; c < 4; c++) acc[r][c] = 0.f;

    const float* hr0 = hsrc + (size_t)(grow0 + rl0 + 0) * FIN;
    const float* hr1 = hsrc + (size_t)(grow0 + rl0 + 1) * FIN;
    const float* hr2 = hsrc + (size_t)(grow0 + rl0 + 2) * FIN;
    const float* hr3 = hsrc + (size_t)(grow0 + rl0 + 3) * FIN;

    for (int kb = 0; kb < FIN; kb += 32) {
        {
            int o = t >> 1, kh = (t & 1) * 16;
#pragma unroll
            for (int s2 = 0; s2 < 4; s2++) {
                float4 v = __ldg((const float4*)(Ww + (size_t)o * FIN + kb + kh + s2 * 4));
                Bs[kh + s2 * 4 + 0][o] = v.x;
                Bs[kh + s2 * 4 + 1][o] = v.y;
                Bs[kh + s2 * 4 + 2][o] = v.z;
                Bs[kh + s2 * 4 + 3][o] = v.w;
            }
        }
        __syncthreads();
#pragma unroll
        for (int k4 = 0; k4 < 32; k4 += 4) {
            float4 a0 = __ldg((const float4*)(hr0 + kb + k4));
            float4 a1 = __ldg((const float4*)(hr1 + kb + k4));
            float4 a2 = __ldg((const float4*)(hr2 + kb + k4));
            float4 a3 = __ldg((const float4*)(hr3 + kb + k4));
            float4 b0 = *(const float4*)&Bs[k4 + 0][col];
            float4 b1 = *(const float4*)&Bs[k4 + 1][col];
            float4 b2 = *(const float4*)&Bs[k4 + 2][col];
            float4 b3 = *(const float4*)&Bs[k4 + 3][col];
#define FMA4(ar, bv) \
            acc[0][0] += a0.ar * bv.x; acc[0][1] += a0.ar * bv.y; \
            acc[0][2] += a0.ar * bv.z; acc[0][3] += a0.ar * bv.w; \
            acc[1][0] += a1.ar * bv.x; acc[1][1] += a1.ar * bv.y; \
            acc[1][2] += a1.ar * bv.z; acc[1][3] += a1.ar * bv.w; \
            acc[2][0] += a2.ar * bv.x; acc[2][1] += a2.ar * bv.y; \
            acc[2][2] += a2.ar * bv.z; acc[2][3] += a2.ar * bv.w; \
            acc[3][0] += a3.ar * bv.x; acc[3][1] += a3.ar * bv.y; \
            acc[3][2] += a3.ar * bv.z; acc[3][3] += a3.ar * bv.w;
            FMA4(x, b0) FMA4(y, b1) FMA4(z, b2) FMA4(w, b3)
#undef FMA4
        }
        __syncthreads();
    }

    {
        float4 bias = __ldg((const float4*)(Wb + col));
#pragma unroll
        for (int r = 0; r < 4; r++) {
            float4 o4 = make_float4(acc[r][0] + bias.x, acc[r][1] + bias.y,
                                    acc[r][2] + bias.z, acc[r][3] + bias.w);
            *(float4*)&Whs[rl0 + r][col] = o4;
        }
    }
    __syncthreads();

    const int b  = grow0 >> 11;
    const int n0 = grow0 & (NN - 1);

    // (a) emit B-fragments (tf32)
    {
        const size_t base = ((size_t)b * (NN / 32) + (n0 >> 5)) * 1024;
#pragma unroll
        for (int q = 0; q < 4; q++) {
            const int s    = q * 256 + t;
            const int lane = s & 31;
            const int ntp  = (s >> 5) & 7;
            const int ks   = s >> 8;
            const int jl   = ks * 8 + (lane & 3);
            const int o0   = ntp * 16 + (lane >> 2);
            g_Bfrag4[base + s] = make_uint4(f2tf32(Whs[jl][o0]),
                                            f2tf32(Whs[jl + 4][o0]),
                                            f2tf32(Whs[jl][o0 + 8]),
                                            f2tf32(Whs[jl + 4][o0 + 8]));
        }
    }

    // (b) el/er dots + exps (exact fp32)
    {
        const int w    = t >> 5;
        const int lane = t & 31;
        float4 al[HH], ar[HH];
#pragma unroll
        for (int hh = 0; hh < HH; hh++) {
            al[hh] = __ldg((const float4*)(attn_w + hh * 2 * FOUT + lane * 4));
            ar[hh] = __ldg((const float4*)(attn_w + hh * 2 * FOUT + FOUT + lane * 4));
        }
#pragma unroll
        for (int r = 0; r < 4; r++) {
            const int rowl = w * 4 + r;
            const int n    = n0 + rowl;
            float4 v = *(const float4*)&Whs[rowl][lane * 4];
#pragma unroll
            for (int hh = 0; hh < HH; hh++) {
                float sl = v.x * al[hh].x + v.y * al[hh].y
                         + v.z * al[hh].z + v.w * al[hh].w;
                float sr = v.x * ar[hh].x + v.y * ar[hh].y
                         + v.z * ar[hh].z + v.w * ar[hh].w;
#pragma unroll
                for (int off = 16; off > 0; off >>= 1) {
                    sl += __shfl_xor_sync(0xffffffffu, sl, off);
                    sr += __shfl_xor_sync(0xffffffffu, sr, off);
                }
                if (lane == 0) {
                    g_iAC[(b * HH + hh) * NN + n] =
                        make_float2(expf(sl), expf(NEG * sl));
                    g_jEFi[((size_t)(b * NN + n)) * HH + hh] =
                        make_float2(expf(sr), expf(NEG * sr));
                }
            }
        }
    }
}

// ---------------------------------------------------------------------------
// Kernel 2: Z pre-pass (smem-tiled j-stream, max-trick).
// ---------------------------------------------------------------------------
__device__ __forceinline__ uint32_t zswz(uint32_t a) {
    return a ^ (((a >> 10) & 7u) << 5);
}
__global__ __launch_bounds__(256) void zsum_kernel()
{
    __shared__ float4 jef[512];
    __shared__ float  zr[32][4][8];
    const int t  = threadIdx.x;
    const int b  = blockIdx.y;
    const int i0 = blockIdx.x * 32;
    const int i  = t >> 3, jq = t & 7;
    const int gi = i0 + i;

    float2 AC[4];
#pragma unroll
    for (int h = 0; h < HH; h++) AC[h] = __ldg(&g_iAC[(b * HH + h) * NN + gi]);

    float z0 = 0.f, z1 = 0.f, z2 = 0.f, z3 = 0.f;
    const float4*   src4 = (const float4*)(g_jEFi + (size_t)b * NN * HH);
    const uint32_t* mrow = g_adjbits + (size_t)gi * 64;
    char* jefc = (char*)jef;

    for (int c0 = 0; c0 < NN; c0 += 256) {
        __syncthreads();
        {
            float4 v0 = __ldg(src4 + (size_t)(c0 + t) * 2);
            float4 v1 = __ldg(src4 + (size_t)(c0 + t) * 2 + 1);
            uint32_t a = zswz((uint32_t)t * 32u);
            *(float4*)(jefc + a)      = v0;
            *(float4*)(jefc + a + 16) = v1;
        }
        __syncthreads();

        const uint32_t mw = __ldg(mrow + (c0 >> 5) + jq);
#pragma unroll 8
        for (int e = 0; e < 32; e++) {
            if ((mw >> e) & 1u) {
                uint32_t a = zswz((uint32_t)(jq * 32 + e) * 32u);
                float4 q01 = *(const float4*)(jefc + a);
                float4 q23 = *(const float4*)(jefc + a + 16);
                z0 += fmaxf(AC[0].x * q01.x, AC[0].y * q01.y);
                z1 += fmaxf(AC[1].x * q01.z, AC[1].y * q01.w);
                z2 += fmaxf(AC[2].x * q23.x, AC[2].y * q23.y);
                z3 += fmaxf(AC[3].x * q23.z, AC[3].y * q23.w);
            }
        }
    }
    __syncthreads();
    zr[i][0][jq] = z0; zr[i][1][jq] = z1; zr[i][2][jq] = z2; zr[i][3][jq] = z3;
    __syncthreads();

    if (t < 128) {
        const int ii = t >> 2, h = t & 3;
        float Z = 0.f;
#pragma unroll
        for (int g = 0; g < 8; g++) Z += zr[ii][h][g];
        float2 ac  = __ldg(&g_iAC[(b * HH + h) * NN + i0 + ii]);
        float  inv = (Z > 0.f) ? 0.25f / Z : 0.f;
        g_irow[(b * HH + h) * NN + i0 + ii] = make_float2(ac.x * inv, ac.y * inv);
    }
}

// ---------------------------------------------------------------------------
// Kernel 3 (main): P_avg @ Wh via mma.sync tf32, M=32, TK=32/iter.
// smem 38KB: Af single 4K | Bf 2x16K | JP 2x1K. 3 CTAs/SM target.
// ---------------------------------------------------------------------------
#define SM_A(mt, ks, ln)    (((mt) * 4 + (ks)) * 32 + (ln))
#define SM_B(p, ks, ntp, ln) ((p) * 1024 + (ks) * 256 + (ntp) * 32 + (ln))
#define OFF_BF 4096
#define OFF_JP 36864
#define SMEM_BYTES 38912

__global__ __launch_bounds__(256, 3) void gat_main_mma(float* __restrict__ out)
{
    extern __shared__ char smem[];
    uint4*  Af  = (uint4*)smem;
    uint4*  Bf  = (uint4*)(smem + OFF_BF);
    float4* JPf = (float4*)(smem + OFF_JP);
    const uint32_t Bf_sa = (uint32_t)__cvta_generic_to_shared(Bf);
    const uint32_t JP_sa = (uint32_t)__cvta_generic_to_shared(JPf);

    const int t    = threadIdx.x;
    const int w    = t >> 5;
    const int lane = t & 31;
    const int mw   = w >> 2;            // m16 tile (gen + consume)
    const int nw   = w & 3;             // consume: 32-col group; gen: ks
    const int b    = blockIdx.y;
    const int i0   = blockIdx.x * 32;

    const int r = lane >> 2;
    const int c = lane & 3;

    const int gia = i0 + mw * 16 + r;
    const int gib = gia + 8;

    float2 RA[4], RB[4];
#pragma unroll
    for (int h = 0; h < HH; h++) {
        RA[h] = __ldg(&g_irow[(b * HH + h) * NN + gia]);
        RB[h] = __ldg(&g_irow[(b * HH + h) * NN + gib]);
    }
    const uint32_t* mba   = g_adjbits + (size_t)gia * 64;
    const uint32_t* mbb   = g_adjbits + (size_t)gib * 64;
    const uint4*    bbase = g_Bfrag4 + (size_t)b * (NN / 32) * 1024;
    const float4*   jsrc  = (const float4*)(g_jEFi + (size_t)b * NN * HH);

    float acc[4][4];
#pragma unroll
    for (int n = 0; n < 4; n++)
#pragma unroll
        for (int k = 0; k < 4; k++) acc[n][k] = 0.f;

    auto stage = [&](int jn, int q) {
        const uint4* src = bbase + (size_t)jn * 1024;
        const uint32_t bdst = Bf_sa + (uint32_t)q * 16384u;
#pragma unroll
        for (int k4 = 0; k4 < 4; k4++)
            cp_async16(bdst + (uint32_t)(k4 * 256 + t) * 16u, src + k4 * 256 + t);
        if (t < 64)
            cp_async16(JP_sa + (uint32_t)(q * 64 + t) * 16u, jsrc + jn * 64 + t);
        CP_COMMIT();
    };

    // each warp generates ONE fragment: (mt = mw, ks = nw)
    auto agen = [&](int p, uint32_t ma, uint32_t mb2) {
        const float4* JP = JPf + p * 64;
        const int jA = nw * 8 + c;
        float4 a01 = JP[jA * 2],       a23 = JP[jA * 2 + 1];
        float4 b01 = JP[(jA + 4) * 2], b23 = JP[(jA + 4) * 2 + 1];

        float vaA = (fmaxf(RA[0].x * a01.x, RA[0].y * a01.y)
                   + fmaxf(RA[1].x * a01.z, RA[1].y * a01.w))
                  + (fmaxf(RA[2].x * a23.x, RA[2].y * a23.y)
                   + fmaxf(RA[3].x * a23.z, RA[3].y * a23.w));
        float vbA = (fmaxf(RB[0].x * a01.x, RB[0].y * a01.y)
                   + fmaxf(RB[1].x * a01.z, RB[1].y * a01.w))
                  + (fmaxf(RB[2].x * a23.x, RB[2].y * a23.y)
                   + fmaxf(RB[3].x * a23.z, RB[3].y * a23.w));
        float vaB = (fmaxf(RA[0].x * b01.x, RA[0].y * b01.y)
                   + fmaxf(RA[1].x * b01.z, RA[1].y * b01.w))
                  + (fmaxf(RA[2].x * b23.x, RA[2].y * b23.y)
                   + fmaxf(RA[3].x * b23.z, RA[3].y * b23.w));
        float vbB = (fmaxf(RB[0].x * b01.x, RB[0].y * b01.y)
                   + fmaxf(RB[1].x * b01.z, RB[1].y * b01.w))
                  + (fmaxf(RB[2].x * b23.x, RB[2].y * b23.y)
                   + fmaxf(RB[3].x * b23.z, RB[3].y * b23.w));

        const int sh = nw * 8 + c;
        vaA = ((ma  >> sh)       & 1u) ? vaA : 0.f;
        vbA = ((mb2 >> sh)       & 1u) ? vbA : 0.f;
        vaB = ((ma  >> (sh + 4)) & 1u) ? vaB : 0.f;
        vbB = ((mb2 >> (sh + 4)) & 1u) ? vbB : 0.f;

        Af[SM_A(mw, nw, lane)] =
            make_uint4(f2tf32(vaA), f2tf32(vbA), f2tf32(vaB), f2tf32(vbB));
    };

    auto consume = [&](int p) {
#pragma unroll
        for (int ks = 0; ks < 4; ks++) {
            uint4 a  = Af[SM_A(mw, ks, lane)];
            uint4 b0 = Bf[SM_B(p, ks, nw * 2 + 0, lane)];
            uint4 b1 = Bf[SM_B(p, ks, nw * 2 + 1, lane)];
            mma_tf32(acc[0][0], acc[0][1], acc[0][2], acc[0][3],
                     a.x, a.y, a.z, a.w, b0.x, b0.y);
            mma_tf32(acc[1][0], acc[1][1], acc[1][2], acc[1][3],
                     a.x, a.y, a.z, a.w, b0.z, b0.w);
            mma_tf32(acc[2][0], acc[2][1], acc[2][2], acc[2][3],
                     a.x, a.y, a.z, a.w, b1.x, b1.y);
            mma_tf32(acc[3][0], acc[3][1], acc[3][2], acc[3][3],
                     a.x, a.y, a.z, a.w, b1.z, b1.w);
        }
    };

    // prologue
    stage(0, 0);
    uint32_t maC = __ldg(mba + 0);
    uint32_t mbC = __ldg(mbb + 0);
    CP_WAIT0();
    __syncthreads();

    // pipelined mainloop (Af single-buffered: write->sync->read->sync)
    for (int jt = 0; jt < NI; jt++) {
        const int p = jt & 1, q = p ^ 1;

        if (jt + 1 < NI) stage(jt + 1, q);

        agen(p, maC, mbC);
        __syncthreads();                 // Af visible

        consume(p);

        if (jt + 1 < NI) {
            maC = __ldg(mba + jt + 1);
            mbC = __ldg(mbb + jt + 1);
            CP_WAIT0();
        }
        __syncthreads();                 // buffer q ready; Af free
    }

    // epilogue: accumulators are final pre-ReLU outputs
    const int rowa = i0 + mw * 16 + r;
#pragma unroll
    for (int nt = 0; nt < 4; nt++) {
        const int col = nw * 32 + nt * 8 + c * 2;
        float* op = out + ((size_t)(b * NN + rowa)) * FOUT + col;
        *(float2*)op = make_float2(fmaxf(acc[nt][0], 0.f), fmaxf(acc[nt][1], 0.f));
        *(float2*)(op + 8 * FOUT) = make_float2(fmaxf(acc[nt][2], 0.f),
                                                fmaxf(acc[nt][3], 0.f));
    }
}

// ---------------------------------------------------------------------------
extern "C" void kernel_launch(void* const* d_in, const int* in_sizes, int n_in,
                              void* d_out, int out_size)
{
    const float* h      = (const float*)d_in[0];
    const int*   adj    = (const int*)d_in[1];
    const float* W_w    = (const float*)d_in[2];
    const float* W_b    = (const float*)d_in[3];
    const float* attn_w = (const float*)d_in[4];
    float* out = (float*)d_out;

    adjbits_kernel<<<NN, 64>>>(adj);
    wh_fused<<<(Bb * NN) / 32, 256>>>(h, W_w, W_b, attn_w);
    zsum_kernel<<<dim3(NN / 32, Bb), 256>>>();

    cudaFuncSetAttribute(gat_main_mma,
                         cudaFuncAttributeMaxDynamicSharedMemorySize, SMEM_BYTES);
    gat_main_mma<<<dim3(NN / 32, Bb), 256, SMEM_BYTES>>>(out);
}